// round 5
// baseline (speedup 1.0000x reference)
#include <cuda_runtime.h>
#include <cuda_fp16.h>
#include <mma.h>
#include <cstdint>

using namespace nvcuda;

#define G      24
#define CIN    512
#define COUT   512
#define BMAX   2048
#define KT     (G * CIN)          // 12288

#define BM 128
#define BN 256
#define BK 32
#define NSTAGE 4
#define NCHUNK (KT / BK)          // 384
#define NTHREADS 512

// padded smem rows
#define LDA (BK + 8)              // 40 halves
#define LDB (BN + 8)              // 264 halves
#define ASTG (BM * LDA * 2)       // 10240 B per stage
#define BSTG (BK * LDB * 2)       // 16896 B per stage
#define SM_BOFF (NSTAGE * ASTG)   // 40960
#define SM_SJ   (SM_BOFF + NSTAGE * BSTG)   // 108544
#define SMEM_TOTAL (SM_SJ + 128)

// ---- scratch (no allocation allowed) --------------------------------------
__device__ __half g_xh[(long)BMAX * G * CIN];   // x fp16 [b][j][c]
__device__ __half g_wt[(long)KT * COUT];        // W^T fp16 [k][o], k = r*CIN+c
__device__ int    g_jmap[G * G];                // jmap[i*G + r] = j

// ---- helpers --------------------------------------------------------------
__device__ __forceinline__ uint32_t smem_u32(const void* p) {
    uint32_t a;
    asm("{ .reg .u64 t; cvta.to.shared.u64 t, %1; cvt.u32.u64 %0, t; }" : "=r"(a) : "l"(p));
    return a;
}
__device__ __forceinline__ void cp_async16(uint32_t saddr, const void* gaddr) {
    asm volatile("cp.async.cg.shared.global [%0], [%1], 16;" :: "r"(saddr), "l"(gaddr) : "memory");
}
__device__ __forceinline__ void cp_commit() {
    asm volatile("cp.async.commit_group;" ::: "memory");
}
template <int N>
__device__ __forceinline__ void cp_wait() {
    asm volatile("cp.async.wait_group %0;" :: "n"(N) : "memory");
}

// ---- prep kernels ---------------------------------------------------------
__global__ void jmap_kernel(const int* __restrict__ pair_orbit) {
    int t = threadIdx.x;
    if (t < G * G) {
        int i = t / G, j = t % G;
        g_jmap[i * G + pair_orbit[i * G + j]] = j;
    }
}

__global__ void convert_x_kernel(const float* __restrict__ x, long n) {
    long idx = ((long)blockIdx.x * blockDim.x + threadIdx.x) * 4;
    if (idx < n) {
        float4 v = *reinterpret_cast<const float4*>(x + idx);
        *reinterpret_cast<__half2*>(g_xh + idx)     = __floats2half2_rn(v.x, v.y);
        *reinterpret_cast<__half2*>(g_xh + idx + 2) = __floats2half2_rn(v.z, v.w);
    }
}

// weight [o, c, r] fp32 -> g_wt [(r*CIN + c) * COUT + o] fp16
__global__ void convert_w_kernel(const float* __restrict__ w, int nr, long n) {
    long t = (long)blockIdx.x * blockDim.x + threadIdx.x;
    if (t < n) {
        int r = (int)(t % nr);
        long t2 = t / nr;
        int c = (int)(t2 % CIN);
        int o = (int)(t2 / CIN);
        g_wt[((long)r * CIN + c) * COUT + o] = __float2half_rn(w[t]);
    }
}

// ---- main GEMM ------------------------------------------------------------
// out[(b,i), o] = sum_k A[(b,i),k] * Wt[k,o];  A row gathered via jmap.
// 512 threads, 16 warps as 4(m) x 4(n), warp tile 32x64; cp.async 4-stage.
__global__ void __launch_bounds__(NTHREADS, 1)
gemm_kernel(float* __restrict__ out, const float* __restrict__ bias, int nbt) {
    extern __shared__ char smem[];
    const uint32_t sb = smem_u32(smem);
    const int tid = threadIdx.x;
    const int wid = tid >> 5;
    const int wm = wid & 3;            // 0..3  -> m offset wm*32
    const int wn = wid >> 2;           // 0..3  -> n offset wn*64

    const int i  = blockIdx.y / nbt;
    const int b0 = (blockIdx.y - i * nbt) * BM;
    const int o0 = blockIdx.x * BN;

    int* sj = (int*)(smem + SM_SJ);
    if (tid < G) sj[tid] = g_jmap[i * G + tid];
    __syncthreads();

    const __half* Abase = g_xh + (long)b0 * (G * CIN);
    const __half* Bbase = g_wt + o0;

    // A: 128 rows x 4 vec -> 1 vec/thread. B: 32 rows x 32 vec -> 2 vec/thread.
    const int am = tid >> 2, akc = tid & 3;
    const uint32_t aoff = sb + (am * LDA + akc * 8) * 2;
    const long agoff = (long)am * (G * CIN) + akc * 8;

    // prologue: stages 0..2
#pragma unroll
    for (int ch = 0; ch < NSTAGE - 1; ch++) {
        const int s = ch;
        const int r = ch >> 4, c0 = (ch & 15) << 5;
        const __half* Ab = Abase + sj[r] * CIN + c0;
        cp_async16(aoff + s * ASTG, Ab + agoff);
        const __half* Bb = Bbase + (long)(ch << 5) * COUT;
#pragma unroll
        for (int v = 0; v < 2; v++) {
            int q = v * NTHREADS + tid;          // 0..1023
            int kk = q >> 5, nc = q & 31;
            cp_async16(sb + SM_BOFF + s * BSTG + (kk * LDB + nc * 8) * 2,
                       Bb + (long)kk * COUT + nc * 8);
        }
        cp_commit();
    }

    wmma::fragment<wmma::accumulator, 16, 16, 16, float> acc[2][4];
#pragma unroll
    for (int a = 0; a < 2; a++)
#pragma unroll
        for (int b = 0; b < 4; b++) wmma::fill_fragment(acc[a][b], 0.0f);

    for (int ch = 0; ch < NCHUNK; ch++) {
        cp_wait<NSTAGE - 2>();
        __syncthreads();

        // prefetch chunk ch+3 into stage (ch+3)%4
        const int pf = ch + NSTAGE - 1;
        if (pf < NCHUNK) {
            const int s = pf & (NSTAGE - 1);
            const int r = pf >> 4, c0 = (pf & 15) << 5;
            const __half* Ab = Abase + sj[r] * CIN + c0;
            cp_async16(aoff + s * ASTG, Ab + agoff);
            const __half* Bb = Bbase + (long)(pf << 5) * COUT;
#pragma unroll
            for (int v = 0; v < 2; v++) {
                int q = v * NTHREADS + tid;
                int kk = q >> 5, nc = q & 31;
                cp_async16(sb + SM_BOFF + s * BSTG + (kk * LDB + nc * 8) * 2,
                           Bb + (long)kk * COUT + nc * 8);
            }
            cp_commit();
        }

        // compute stage ch%4
        const int s = ch & (NSTAGE - 1);
        const __half* As = (const __half*)(smem + s * ASTG);
        const __half* Bs = (const __half*)(smem + SM_BOFF + s * BSTG);
#pragma unroll
        for (int ks = 0; ks < BK; ks += 16) {
            wmma::fragment<wmma::matrix_a, 16, 16, 16, __half, wmma::row_major> af[2];
#pragma unroll
            for (int a = 0; a < 2; a++)
                wmma::load_matrix_sync(af[a], As + (wm * 32 + a * 16) * LDA + ks, LDA);
#pragma unroll
            for (int b = 0; b < 4; b++) {
                wmma::fragment<wmma::matrix_b, 16, 16, 16, __half, wmma::row_major> bf;
                wmma::load_matrix_sync(bf, Bs + ks * LDB + wn * 64 + b * 16, LDB);
#pragma unroll
                for (int a = 0; a < 2; a++)
                    wmma::mma_sync(acc[a][b], af[a], bf, acc[a][b]);
            }
        }
    }

    // ---- epilogue: fused bias add ----
    // stages are dead now; build a 16-row replicated bias tile in smem.
    __syncthreads();
    float* bt = (float*)smem;                       // 16 x BN floats = 16 KB
    {
        float bv = bias[o0 + (tid & 255)];
#pragma unroll
        for (int rr = (tid >> 8); rr < 16; rr += 2)  // 2 row-groups per thread pair
            bt[rr * BN + (tid & 255)] = bv;
    }
    __syncthreads();

#pragma unroll
    for (int a = 0; a < 2; a++)
#pragma unroll
        for (int b = 0; b < 4; b++) {
            wmma::fragment<wmma::accumulator, 16, 16, 16, float> bfr;
            wmma::load_matrix_sync(bfr, bt + wn * 64 + b * 16, BN, wmma::mem_row_major);
#pragma unroll
            for (int e = 0; e < bfr.num_elements; e++) acc[a][b].x[e] += bfr.x[e];
            int m = b0 + wm * 32 + a * 16;
            int o = o0 + wn * 64 + b * 16;
            float* p = out + ((long)m * G + i) * COUT + o;
            wmma::store_matrix_sync(p, acc[a][b], (unsigned)(G * COUT), wmma::mem_row_major);
        }
}

// ---------------------------------------------------------------------------
extern "C" void kernel_launch(void* const* d_in, const int* in_sizes, int n_in,
                              void* d_out, int out_size) {
    const float* x          = (const float*)d_in[0];
    const float* weight     = (const float*)d_in[1];
    const float* bias       = (const float*)d_in[2];
    const int*   pair_orbit = (const int*)d_in[3];
    float* out = (float*)d_out;

    const long xn  = (long)in_sizes[0];
    const long wn  = (long)in_sizes[1];
    const int  nr  = (int)(wn / ((long)COUT * CIN));   // 24
    const int  Bsz = (int)(xn / ((long)G * CIN));      // 2048
    const int  nbt = Bsz / BM;                         // 16

    jmap_kernel<<<1, G * G>>>(pair_orbit);
    convert_x_kernel<<<(unsigned)((xn / 4 + 255) / 256), 256>>>(x, xn);
    convert_w_kernel<<<(unsigned)((wn + 255) / 256), 256>>>(weight, nr, wn);

    cudaFuncSetAttribute(gemm_kernel, cudaFuncAttributeMaxDynamicSharedMemorySize,
                         SMEM_TOTAL);
    dim3 grid(COUT / BN, G * nbt);    // 2 x 384 = 768 CTAs
    gemm_kernel<<<grid, NTHREADS, SMEM_TOTAL>>>(out, bias, nbt);
}